// round 1
// baseline (speedup 1.0000x reference)
#include <cuda_runtime.h>
#include <cstdint>

// Problem constants
#define B   16
#define C   512
#define N   2304          // 48*48
#define TN  64            // n-tile
#define TM  64            // m-tile
#define TK  16            // k-chunk (fp32 elems)

typedef unsigned long long ull;

// Scratch (no allocations allowed -> __device__ globals)
__device__ float g_flat[(size_t)B * N * C];   // [b][n][c]  normalized, transposed
__device__ float g_att [B * N];
__device__ float g_inv [B * N];
__device__ float g_ref [B * N];

// ---------------------------------------------------------------------------
// Kernel A1: per-(b,n) sumsq + dot(w) -> inv_norm, att = softplus(dot)
// grid (9, 16), block 256. Thread owns one n, loops c (coalesced over n).
// ---------------------------------------------------------------------------
__global__ void __launch_bounds__(256) kA1(const float* __restrict__ x,
                                           const float* __restrict__ w) {
    __shared__ float ws[C];
    int tid = threadIdx.x;
    for (int i = tid; i < C; i += 256) ws[i] = w[i];
    __syncthreads();

    int b = blockIdx.y;
    int n = blockIdx.x * 256 + tid;
    const float* xb = x + (size_t)b * C * N + n;

    float ss = 0.f, dt = 0.f;
#pragma unroll 8
    for (int c = 0; c < C; ++c) {
        float v = xb[(size_t)c * N];
        ss = fmaf(v, v, ss);
        dt = fmaf(v, ws[c], dt);
    }
    float nrm = sqrtf(ss);
    g_inv[b * N + n] = 1.f / fmaxf(nrm, 1e-12f);
    float ad = fabsf(dt);
    g_att[b * N + n] = fmaxf(dt, 0.f) + log1pf(expf(-ad));  // stable softplus
}

// ---------------------------------------------------------------------------
// Kernel A2: normalize + transpose:  g_flat[b][n][c] = x[b][c][n] * inv[b][n]
// grid (72, 16, 16) = (n/32, c/32, b), block (32, 8)
// ---------------------------------------------------------------------------
__global__ void __launch_bounds__(256) kA2(const float* __restrict__ x) {
    __shared__ float tile[32][33];
    int n0 = blockIdx.x * 32;
    int c0 = blockIdx.y * 32;
    int b  = blockIdx.z;
    int txx = threadIdx.x, tyy = threadIdx.y;

#pragma unroll
    for (int r = 0; r < 4; ++r) {
        int c = c0 + tyy + r * 8;
        tile[tyy + r * 8][txx] = x[((size_t)b * C + c) * N + n0 + txx];
    }
    __syncthreads();
#pragma unroll
    for (int r = 0; r < 4; ++r) {
        int n = n0 + tyy + r * 8;
        g_flat[((size_t)b * N + n) * C + c0 + txx] =
            tile[txx][tyy + r * 8] * g_inv[b * N + n];
    }
}

// ---------------------------------------------------------------------------
// Kernel B: refine[b,n] = sum_m relu(flat_n . flat_m)^2 * att[b,m]
// grid (36, 16) = (n/64, b), block 256 (16x16 threads, 4x4 micro-tile).
// Packed-k f32x2 FMAs: acc holds (even-k partial, odd-k partial).
// ---------------------------------------------------------------------------
__device__ __forceinline__ void fma2(ull& d, ull a, ull bb) {
    asm("fma.rn.f32x2 %0, %1, %2, %0;" : "+l"(d) : "l"(a), "l"(bb));
}
__device__ __forceinline__ float lo32(ull v) { return __uint_as_float((unsigned)(v & 0xffffffffull)); }
__device__ __forceinline__ float hi32(ull v) { return __uint_as_float((unsigned)(v >> 32)); }

__global__ void __launch_bounds__(256) kB() {
    __shared__ __align__(16) float2 As[TK / 2][TN];   // [k2][row] (k-pair packed)
    __shared__ __align__(16) float2 Bs[TK / 2][TM];
    __shared__ float attS[TM];
    __shared__ float red[TN][17];

    int b  = blockIdx.y;
    int n0 = blockIdx.x * TN;
    int tid = threadIdx.x;
    int tx = tid & 15, ty = tid >> 4;   // 16x16
    int lrow = tid >> 2, lq = tid & 3;  // loader: 64 rows x 4 quads

    const float* base = g_flat + (size_t)b * N * C;
    const float* attb = g_att + b * N;

    float rf[4] = {0.f, 0.f, 0.f, 0.f};

    for (int m0 = 0; m0 < N; m0 += TM) {
        ull acc[4][4];
#pragma unroll
        for (int i = 0; i < 4; ++i)
#pragma unroll
            for (int j = 0; j < 4; ++j) acc[i][j] = 0ull;

        for (int k0 = 0; k0 < C; k0 += TK) {
            float4 va = *(const float4*)(base + ((size_t)(n0 + lrow)) * C + k0 + lq * 4);
            float4 vb = *(const float4*)(base + ((size_t)(m0 + lrow)) * C + k0 + lq * 4);
            __syncthreads();   // previous compute / epilogue reads done
            As[lq * 2][lrow]     = make_float2(va.x, va.y);
            As[lq * 2 + 1][lrow] = make_float2(va.z, va.w);
            Bs[lq * 2][lrow]     = make_float2(vb.x, vb.y);
            Bs[lq * 2 + 1][lrow] = make_float2(vb.z, vb.w);
            if (k0 == 0 && tid < TM) attS[tid] = attb[m0 + tid];
            __syncthreads();

#pragma unroll
            for (int k2 = 0; k2 < TK / 2; ++k2) {
                ulonglong2 a01 = *(const ulonglong2*)&As[k2][ty * 4];
                ulonglong2 a23 = *(const ulonglong2*)&As[k2][ty * 4 + 2];
                ulonglong2 b01 = *(const ulonglong2*)&Bs[k2][tx * 4];
                ulonglong2 b23 = *(const ulonglong2*)&Bs[k2][tx * 4 + 2];
                ull a2[4] = {a01.x, a01.y, a23.x, a23.y};
                ull b2[4] = {b01.x, b01.y, b23.x, b23.y};
#pragma unroll
                for (int i = 0; i < 4; ++i)
#pragma unroll
                    for (int j = 0; j < 4; ++j) fma2(acc[i][j], a2[i], b2[j]);
            }
        }
        // epilogue for this m-tile
        float av[4];
#pragma unroll
        for (int j = 0; j < 4; ++j) av[j] = attS[tx * 4 + j];
#pragma unroll
        for (int i = 0; i < 4; ++i) {
#pragma unroll
            for (int j = 0; j < 4; ++j) {
                float sim = lo32(acc[i][j]) + hi32(acc[i][j]);
                float r = fmaxf(sim, 0.f);
                rf[i] = fmaf(r * r, av[j], rf[i]);
            }
        }
    }

    // reduce rf over tx (16 threads per row)
    __syncthreads();
#pragma unroll
    for (int i = 0; i < 4; ++i) red[ty * 4 + i][tx] = rf[i];
    __syncthreads();
    if (tid < TN) {
        float s = 0.f;
#pragma unroll
        for (int t = 0; t < 16; ++t) s += red[tid][t];
        g_ref[b * N + n0 + tid] = s;
    }
}

// ---------------------------------------------------------------------------
// Kernel C: out[b,c] = (1/N) * sum_n x[b][c][n] * refine[b][n]
// grid 16*64 = 1024, block 256 (8 warps, one warp per c)
// ---------------------------------------------------------------------------
__global__ void __launch_bounds__(256) kC(const float* __restrict__ x,
                                          float* __restrict__ out) {
    int b  = blockIdx.x >> 6;
    int cg = blockIdx.x & 63;
    int warp = threadIdx.x >> 5, lane = threadIdx.x & 31;
    int c = cg * 8 + warp;

    const float* xr = x + ((size_t)b * C + c) * N;
    const float* rf = g_ref + b * N;

    float s = 0.f;
#pragma unroll 4
    for (int n = lane; n < N; n += 32) s = fmaf(xr[n], rf[n], s);
#pragma unroll
    for (int off = 16; off > 0; off >>= 1)
        s += __shfl_down_sync(0xffffffffu, s, off);
    if (lane == 0) out[b * C + c] = s * (1.0f / (float)N);
}

// ---------------------------------------------------------------------------
extern "C" void kernel_launch(void* const* d_in, const int* in_sizes, int n_in,
                              void* d_out, int out_size) {
    const float* x = (const float*)d_in[0];
    const float* w = (const float*)d_in[1];
    float* out = (float*)d_out;

    kA1<<<dim3(N / 256, B), 256>>>(x, w);
    kA2<<<dim3(N / 32, C / 32, B), dim3(32, 8)>>>(x);
    kB <<<dim3(N / TN, B), 256>>>();
    kC <<<B * 64, 256>>>(x, out);
}

// round 3
// speedup vs baseline: 3.8399x; 3.8399x over previous
#include <cuda_runtime.h>
#include <cstdint>

// Problem constants
#define B    16
#define C    512
#define N    2304          // 48*48
#define TT   128           // block tile (n and m)
#define NT   (N / TT)      // 18 tiles
#define NPAIR (NT * (NT + 1) / 2)   // 171
#define TK   32            // k-chunk (fp32 elems)
#define TK2  (TK / 2)      // 16 packed k2 steps
#define TTP  (TT + 2)      // padded float2 row length

typedef unsigned long long ull;

// Scratch (no allocations allowed -> __device__ globals)
__device__ float g_flat[(size_t)B * N * C];   // [b][n][c]  normalized, transposed
__device__ float g_att [B * N];
__device__ float g_inv [B * N];
__device__ float g_ref [B * N];

// ---------------------------------------------------------------------------
// Kernel A1: per-(b,n) sumsq + dot(w) -> inv_norm, att = softplus(dot)
// Also zeroes g_ref for kB's atomics.
// ---------------------------------------------------------------------------
__global__ void __launch_bounds__(256) kA1(const float* __restrict__ x,
                                           const float* __restrict__ w) {
    __shared__ float ws[C];
    int tid = threadIdx.x;
    for (int i = tid; i < C; i += 256) ws[i] = w[i];
    __syncthreads();

    int b = blockIdx.y;
    int n = blockIdx.x * 256 + tid;
    const float* xb = x + (size_t)b * C * N + n;

    float ss = 0.f, dt = 0.f;
#pragma unroll 8
    for (int c = 0; c < C; ++c) {
        float v = xb[(size_t)c * N];
        ss = fmaf(v, v, ss);
        dt = fmaf(v, ws[c], dt);
    }
    float nrm = sqrtf(ss);
    g_inv[b * N + n] = 1.f / fmaxf(nrm, 1e-12f);
    float ad = fabsf(dt);
    g_att[b * N + n] = fmaxf(dt, 0.f) + log1pf(expf(-ad));  // stable softplus
    g_ref[b * N + n] = 0.f;
}

// ---------------------------------------------------------------------------
// Kernel A2: normalize + transpose:  g_flat[b][n][c] = x[b][c][n] * inv[b][n]
// ---------------------------------------------------------------------------
__global__ void __launch_bounds__(256) kA2(const float* __restrict__ x) {
    __shared__ float tile[32][33];
    int n0 = blockIdx.x * 32;
    int c0 = blockIdx.y * 32;
    int b  = blockIdx.z;
    int txx = threadIdx.x, tyy = threadIdx.y;

#pragma unroll
    for (int r = 0; r < 4; ++r) {
        int c = c0 + tyy + r * 8;
        tile[tyy + r * 8][txx] = x[((size_t)b * C + c) * N + n0 + txx];
    }
    __syncthreads();
#pragma unroll
    for (int r = 0; r < 4; ++r) {
        int n = n0 + tyy + r * 8;
        g_flat[((size_t)b * N + n) * C + c0 + txx] =
            tile[txx][tyy + r * 8] * g_inv[b * N + n];
    }
}

// ---------------------------------------------------------------------------
// Kernel B: symmetric tile-pair GEMM.
// One block per (batch, tile-pair(i<=j)). 256 threads, 8x8 micro-tile with
// f32x2 packed-k accumulators. Off-diagonal pairs emit BOTH row sums
// (-> refine[n in tile i], weighted by att[m]) and col sums
// (-> refine[m in tile j], weighted by att[n]). atomicAdd into g_ref.
// ---------------------------------------------------------------------------
__device__ __forceinline__ void fma2(ull& d, ull a, ull bb) {
    asm("fma.rn.f32x2 %0, %1, %2, %0;" : "+l"(d) : "l"(a), "l"(bb));
}
__device__ __forceinline__ float lo32(ull v) { return __uint_as_float((unsigned)(v & 0xffffffffull)); }
__device__ __forceinline__ float hi32(ull v) { return __uint_as_float((unsigned)(v >> 32)); }

__global__ void __launch_bounds__(256, 1) kB() {
    __shared__ __align__(16) float2 As[TK2][TTP];   // [k2][row], padded
    __shared__ __align__(16) float2 Bs[TK2][TTP];
    __shared__ float attA[TT], attB[TT];
    __shared__ float red[TT][17];

    int b = blockIdx.y;
    // decode pair index -> (ti, tj) with ti <= tj
    int p = blockIdx.x, ti = 0;
    while (p >= NT - ti) { p -= NT - ti; ++ti; }
    int tj = ti + p;
    bool diag = (ti == tj);

    int n0 = ti * TT, m0 = tj * TT;
    int tid = threadIdx.x;
    int tx = tid & 15, ty = tid >> 4;        // 16x16 compute grid
    int lrow = tid >> 3, lq = tid & 7;       // loader: 32 rows x 8 quads per pass

    const float* base = g_flat + (size_t)b * N * C;
    const float* attb = g_att + b * N;

    if (tid < TT)            attA[tid]       = attb[n0 + tid];
    else                     attB[tid - TT]  = attb[m0 + tid - TT];

    ull acc[8][8];
#pragma unroll
    for (int i = 0; i < 8; ++i)
#pragma unroll
        for (int j = 0; j < 8; ++j) acc[i][j] = 0ull;

    for (int k0 = 0; k0 < C; k0 += TK) {
        float4 va[4], vb[4];
#pragma unroll
        for (int pss = 0; pss < 4; ++pss) {
            int row = pss * 32 + lrow;
            va[pss] = *(const float4*)(base + (size_t)(n0 + row) * C + k0 + lq * 4);
            vb[pss] = *(const float4*)(base + (size_t)(m0 + row) * C + k0 + lq * 4);
        }
        __syncthreads();   // prior compute done reading smem
#pragma unroll
        for (int pss = 0; pss < 4; ++pss) {
            int row = pss * 32 + lrow;
            As[lq * 2][row]     = make_float2(va[pss].x, va[pss].y);
            As[lq * 2 + 1][row] = make_float2(va[pss].z, va[pss].w);
            Bs[lq * 2][row]     = make_float2(vb[pss].x, vb[pss].y);
            Bs[lq * 2 + 1][row] = make_float2(vb[pss].z, vb[pss].w);
        }
        __syncthreads();

#pragma unroll
        for (int k2 = 0; k2 < TK2; ++k2) {
            ull a2[8], b2[8];
#pragma unroll
            for (int i = 0; i < 8; ++i) a2[i] = *(const ull*)&As[k2][ty + 16 * i];
#pragma unroll
            for (int j = 0; j < 8; ++j) b2[j] = *(const ull*)&Bs[k2][tx + 16 * j];
#pragma unroll
            for (int i = 0; i < 8; ++i)
#pragma unroll
                for (int j = 0; j < 8; ++j) fma2(acc[i][j], a2[i], b2[j]);
        }
    }

    // ---- epilogue: relu^2 * att, split into row and col partial sums ----
    float av_a[8], av_b[8];
#pragma unroll
    for (int i = 0; i < 8; ++i) av_a[i] = attA[ty + 16 * i];
#pragma unroll
    for (int j = 0; j < 8; ++j) av_b[j] = attB[tx + 16 * j];

    float rf_row[8], rf_col[8];
#pragma unroll
    for (int i = 0; i < 8; ++i) { rf_row[i] = 0.f; rf_col[i] = 0.f; }

#pragma unroll
    for (int i = 0; i < 8; ++i)
#pragma unroll
        for (int j = 0; j < 8; ++j) {
            float sim = lo32(acc[i][j]) + hi32(acc[i][j]);
            float r = fmaxf(sim, 0.f);
            float s = r * r;
            rf_row[i] = fmaf(s, av_b[j], rf_row[i]);
            rf_col[j] = fmaf(s, av_a[i], rf_col[j]);
        }

    float* refb = g_ref + b * N;

    // row sums -> refine[n0 + row], row = ty + 16i, reduce over tx
    __syncthreads();
#pragma unroll
    for (int i = 0; i < 8; ++i) red[ty + 16 * i][tx] = rf_row[i];
    __syncthreads();
    if (tid < TT) {
        float s = 0.f;
#pragma unroll
        for (int t = 0; t < 16; ++t) s += red[tid][t];
        atomicAdd(&refb[n0 + tid], s);
    }

    if (!diag) {
        // col sums -> refine[m0 + col], col = tx + 16j, reduce over ty
        __syncthreads();
#pragma unroll
        for (int j = 0; j < 8; ++j) red[tx + 16 * j][ty] = rf_col[j];
        __syncthreads();
        if (tid < TT) {
            float s = 0.f;
#pragma unroll
            for (int t = 0; t < 16; ++t) s += red[tid][t];
            atomicAdd(&refb[m0 + tid], s);
        }
    }
}

// ---------------------------------------------------------------------------
// Kernel C: out[b,c] = (1/N) * sum_n x[b][c][n] * refine[b][n]
// ---------------------------------------------------------------------------
__global__ void __launch_bounds__(256) kC(const float* __restrict__ x,
                                          float* __restrict__ out) {
    int b  = blockIdx.x >> 6;
    int cg = blockIdx.x & 63;
    int warp = threadIdx.x >> 5, lane = threadIdx.x & 31;
    int c = cg * 8 + warp;

    const float* xr = x + ((size_t)b * C + c) * N;
    const float* rf = g_ref + b * N;

    float s = 0.f;
#pragma unroll 4
    for (int n = lane; n < N; n += 32) s = fmaf(xr[n], rf[n], s);
#pragma unroll
    for (int off = 16; off > 0; off >>= 1)
        s += __shfl_down_sync(0xffffffffu, s, off);
    if (lane == 0) out[b * C + c] = s * (1.0f / (float)N);
}

// ---------------------------------------------------------------------------
extern "C" void kernel_launch(void* const* d_in, const int* in_sizes, int n_in,
                              void* d_out, int out_size) {
    const float* x = (const float*)d_in[0];
    const float* w = (const float*)d_in[1];
    float* out = (float*)d_out;

    kA1<<<dim3(N / 256, B), 256>>>(x, w);
    kA2<<<dim3(N / 32, C / 32, B), dim3(32, 8)>>>(x);
    kB <<<dim3(NPAIR, B), 256>>>();
    kC <<<B * 64, 256>>>(x, out);
}

// round 6
// speedup vs baseline: 10.3354x; 2.6916x over previous
#include <cuda_runtime.h>
#include <cstdint>

// Problem constants
#define B    16
#define C    512
#define N    2304          // 48*48
#define TT   128           // tile (both n and m)
#define NT   (N / TT)      // 18
#define NPAIR (NT * (NT + 1) / 2)   // 171
#define TK   32            // k per chunk
#define NKC  (C / TK)      // 16
#define PITCH 36           // smem row pitch (floats): conflict-free frags, 16B-aligned

// Scratch
__device__ float g_flat[(size_t)B * N * C];   // [b][n][c], tf32-rounded
__device__ float g_att [B * N];
__device__ float g_inv [B * N];
__device__ float g_ref [B * N];

// ---------------------------------------------------------------------------
// Kernel A1: inv_norm + att = softplus(x . w); zero g_ref
// ---------------------------------------------------------------------------
__global__ void __launch_bounds__(256) kA1(const float* __restrict__ x,
                                           const float* __restrict__ w) {
    __shared__ float ws[C];
    int tid = threadIdx.x;
    for (int i = tid; i < C; i += 256) ws[i] = w[i];
    __syncthreads();

    int b = blockIdx.y;
    int n = blockIdx.x * 256 + tid;
    const float* xb = x + (size_t)b * C * N + n;

    float ss = 0.f, dt = 0.f;
#pragma unroll 8
    for (int c = 0; c < C; ++c) {
        float v = xb[(size_t)c * N];
        ss = fmaf(v, v, ss);
        dt = fmaf(v, ws[c], dt);
    }
    float nrm = sqrtf(ss);
    g_inv[b * N + n] = 1.f / fmaxf(nrm, 1e-12f);
    float ad = fabsf(dt);
    g_att[b * N + n] = fmaxf(dt, 0.f) + log1pf(expf(-ad));
    g_ref[b * N + n] = 0.f;
}

// ---------------------------------------------------------------------------
// Kernel A2: normalize + transpose + round-to-nearest tf32
// ---------------------------------------------------------------------------
__global__ void __launch_bounds__(256) kA2(const float* __restrict__ x) {
    __shared__ float tile[32][33];
    int n0 = blockIdx.x * 32;
    int c0 = blockIdx.y * 32;
    int b  = blockIdx.z;
    int txx = threadIdx.x, tyy = threadIdx.y;

#pragma unroll
    for (int r = 0; r < 4; ++r) {
        int c = c0 + tyy + r * 8;
        tile[tyy + r * 8][txx] = x[((size_t)b * C + c) * N + n0 + txx];
    }
    __syncthreads();
#pragma unroll
    for (int r = 0; r < 4; ++r) {
        int n = n0 + tyy + r * 8;
        float v = tile[txx][tyy + r * 8] * g_inv[b * N + n];
        uint32_t u;
        asm("cvt.rna.tf32.f32 %0, %1;" : "=r"(u) : "f"(v));
        g_flat[((size_t)b * N + n) * C + c0 + txx] = __uint_as_float(u);
    }
}

// ---------------------------------------------------------------------------
// Kernel B: symmetric tile-pair GEMM via mma.sync tf32 (m16n8k8).
// 8 warps: warp grid 2(m) x 4(n); each warp 64x32 = 4x4 fragments.
// ---------------------------------------------------------------------------
__device__ __forceinline__ void mma_tf32(float* d, const uint32_t* a,
                                         const uint32_t* bb) {
    asm volatile(
        "mma.sync.aligned.m16n8k8.row.col.f32.tf32.tf32.f32 "
        "{%0,%1,%2,%3}, {%4,%5,%6,%7}, {%8,%9}, {%0,%1,%2,%3};"
        : "+f"(d[0]), "+f"(d[1]), "+f"(d[2]), "+f"(d[3])
        : "r"(a[0]), "r"(a[1]), "r"(a[2]), "r"(a[3]), "r"(bb[0]), "r"(bb[1]));
}

__global__ void __launch_bounds__(256, 2) kB_mma() {
    __shared__ float As[TT][PITCH];
    __shared__ float Bs[TT][PITCH];
    __shared__ float attA[TT], attB[TT];
    __shared__ float rowsum[TT], colsum[TT];

    int b = blockIdx.y;
    int p = blockIdx.x, ti = 0;
    while (p >= NT - ti) { p -= NT - ti; ++ti; }
    int tj = ti + p;
    bool diag = (ti == tj);
    int n0 = ti * TT, m0 = tj * TT;

    int tid  = threadIdx.x;
    int wid  = tid >> 5, lane = tid & 31;
    int grp  = lane >> 2, qid = lane & 3;
    int mw   = (wid & 1) * 64;        // warp m-offset
    int nw   = (wid >> 1) * 32;       // warp n-offset

    const float* attb = g_att + b * N;
    if (tid < TT) { attA[tid] = attb[n0 + tid]; rowsum[tid] = 0.f; }
    else          { attB[tid - TT] = attb[m0 + tid - TT]; colsum[tid - TT] = 0.f; }

    const float* Arow = g_flat + ((size_t)b * N + n0) * C;
    const float* Brow = g_flat + ((size_t)b * N + m0) * C;

    int lrow = tid >> 3, lq = tid & 7;   // loader: 32 rows x 8 quads per pass

    float acc[4][4][4];
#pragma unroll
    for (int i = 0; i < 4; ++i)
#pragma unroll
        for (int j = 0; j < 4; ++j)
#pragma unroll
            for (int r = 0; r < 4; ++r) acc[i][j][r] = 0.f;

    for (int kc = 0; kc < NKC; ++kc) {
        int k0 = kc * TK;
        float4 ra[4], rb[4];
#pragma unroll
        for (int it = 0; it < 4; ++it) {
            int row = it * 32 + lrow;
            ra[it] = *(const float4*)(Arow + (size_t)row * C + k0 + lq * 4);
            rb[it] = *(const float4*)(Brow + (size_t)row * C + k0 + lq * 4);
        }
        __syncthreads();   // previous compute done reading smem
#pragma unroll
        for (int it = 0; it < 4; ++it) {
            int row = it * 32 + lrow;
            *(float4*)&As[row][lq * 4] = ra[it];
            *(float4*)&Bs[row][lq * 4] = rb[it];
        }
        __syncthreads();

#pragma unroll
        for (int ks = 0; ks < 4; ++ks) {
            int kb = ks * 8;
            uint32_t af[4][4], bf[4][2];
#pragma unroll
            for (int fi = 0; fi < 4; ++fi) {
                int r0 = mw + fi * 16 + grp;
                af[fi][0] = __float_as_uint(As[r0][kb + qid]);
                af[fi][1] = __float_as_uint(As[r0 + 8][kb + qid]);
                af[fi][2] = __float_as_uint(As[r0][kb + qid + 4]);
                af[fi][3] = __float_as_uint(As[r0 + 8][kb + qid + 4]);
            }
#pragma unroll
            for (int fj = 0; fj < 4; ++fj) {
                int rn = nw + fj * 8 + grp;
                bf[fj][0] = __float_as_uint(Bs[rn][kb + qid]);
                bf[fj][1] = __float_as_uint(Bs[rn][kb + qid + 4]);
            }
#pragma unroll
            for (int fi = 0; fi < 4; ++fi)
#pragma unroll
                for (int fj = 0; fj < 4; ++fj)
                    mma_tf32(acc[fi][fj], af[fi], bf[fj]);
        }
    }
    __syncthreads();

    // ---- epilogue: relu^2 * att -> per-thread partials -> smem atomics ----
    float rs[4][2], cs[4][2];
#pragma unroll
    for (int i = 0; i < 4; ++i) { rs[i][0] = rs[i][1] = 0.f; cs[i][0] = cs[i][1] = 0.f; }

#pragma unroll
    for (int fi = 0; fi < 4; ++fi) {
        int r0 = mw + fi * 16 + grp, r1 = r0 + 8;
        float aA0 = attA[r0], aA1 = attA[r1];
#pragma unroll
        for (int fj = 0; fj < 4; ++fj) {
            int c0 = nw + fj * 8 + qid * 2, c1 = c0 + 1;
            float s00 = fmaxf(acc[fi][fj][0], 0.f); s00 *= s00;
            float s01 = fmaxf(acc[fi][fj][1], 0.f); s01 *= s01;
            float s10 = fmaxf(acc[fi][fj][2], 0.f); s10 *= s10;
            float s11 = fmaxf(acc[fi][fj][3], 0.f); s11 *= s11;
            float aB0 = attB[c0], aB1 = attB[c1];
            rs[fi][0] = fmaf(s00, aB0, fmaf(s01, aB1, rs[fi][0]));
            rs[fi][1] = fmaf(s10, aB0, fmaf(s11, aB1, rs[fi][1]));
            cs[fj][0] = fmaf(s00, aA0, fmaf(s10, aA1, cs[fj][0]));
            cs[fj][1] = fmaf(s01, aA0, fmaf(s11, aA1, cs[fj][1]));
        }
    }
#pragma unroll
    for (int fi = 0; fi < 4; ++fi) {
        int r0 = mw + fi * 16 + grp;
        atomicAdd(&rowsum[r0], rs[fi][0]);
        atomicAdd(&rowsum[r0 + 8], rs[fi][1]);
    }
    if (!diag) {
#pragma unroll
        for (int fj = 0; fj < 4; ++fj) {
            int c0 = nw + fj * 8 + qid * 2;
            atomicAdd(&colsum[c0], cs[fj][0]);
            atomicAdd(&colsum[c0 + 1], cs[fj][1]);
        }
    }
    __syncthreads();

    float* refb = g_ref + b * N;
    if (tid < TT) {
        atomicAdd(&refb[n0 + tid], rowsum[tid]);
        if (!diag) atomicAdd(&refb[m0 + tid], colsum[tid]);
    }
}

// ---------------------------------------------------------------------------
// Kernel C: out[b,c] = (1/N) * sum_n x[b][c][n] * refine[b][n]
// ---------------------------------------------------------------------------
__global__ void __launch_bounds__(256) kC(const float* __restrict__ x,
                                          float* __restrict__ out) {
    int b  = blockIdx.x >> 6;
    int cg = blockIdx.x & 63;
    int warp = threadIdx.x >> 5, lane = threadIdx.x & 31;
    int c = cg * 8 + warp;

    const float* xr = x + ((size_t)b * C + c) * N;
    const float* rf = g_ref + b * N;

    float s = 0.f;
#pragma unroll 4
    for (int n = lane; n < N; n += 32) s = fmaf(xr[n], rf[n], s);
#pragma unroll
    for (int off = 16; off > 0; off >>= 1)
        s += __shfl_down_sync(0xffffffffu, s, off);
    if (lane == 0) out[b * C + c] = s * (1.0f / (float)N);
}

// ---------------------------------------------------------------------------
extern "C" void kernel_launch(void* const* d_in, const int* in_sizes, int n_in,
                              void* d_out, int out_size) {
    const float* x = (const float*)d_in[0];
    const float* w = (const float*)d_in[1];
    float* out = (float*)d_out;

    kA1<<<dim3(N / 256, B), 256>>>(x, w);
    kA2<<<dim3(N / 32, C / 32, B), dim3(32, 8)>>>(x);
    kB_mma<<<dim3(NPAIR, B), 256>>>();
    kC<<<B * 64, 256>>>(x, out);
}

// round 9
// speedup vs baseline: 13.4513x; 1.3015x over previous
#include <cuda_runtime.h>
#include <cuda_bf16.h>
#include <cstdint>

// Problem constants
#define B    16
#define C    512
#define N    2304          // 48*48
#define TT   128           // tile (both n and m)
#define NT   (N / TT)      // 18
#define NPAIR (NT * (NT + 1) / 2)   // 171
#define TK   32            // k per chunk (bf16 elems)
#define NKC  (C / TK)      // 16

// Scratch
__device__ __nv_bfloat16 g_flat[(size_t)B * N * C];   // [b][n][c] normalized bf16
__device__ float g_att [B * N];
__device__ float g_inv [B * N];
__device__ float g_ref [B * N];

// ---------------------------------------------------------------------------
// Kernel A1: inv_norm + att = softplus(x . w); zero g_ref
// ---------------------------------------------------------------------------
__global__ void __launch_bounds__(256) kA1(const float* __restrict__ x,
                                           const float* __restrict__ w) {
    __shared__ float ws[C];
    int tid = threadIdx.x;
    for (int i = tid; i < C; i += 256) ws[i] = w[i];
    __syncthreads();

    int b = blockIdx.y;
    int n = blockIdx.x * 256 + tid;
    const float* xb = x + (size_t)b * C * N + n;

    float ss = 0.f, dt = 0.f;
#pragma unroll 8
    for (int c = 0; c < C; ++c) {
        float v = xb[(size_t)c * N];
        ss = fmaf(v, v, ss);
        dt = fmaf(v, ws[c], dt);
    }
    float nrm = sqrtf(ss);
    g_inv[b * N + n] = 1.f / fmaxf(nrm, 1e-12f);
    float ad = fabsf(dt);
    g_att[b * N + n] = fmaxf(dt, 0.f) + log1pf(expf(-ad));
    g_ref[b * N + n] = 0.f;
}

// ---------------------------------------------------------------------------
// Kernel A2: normalize + transpose + round to bf16
// ---------------------------------------------------------------------------
__global__ void __launch_bounds__(256) kA2(const float* __restrict__ x) {
    __shared__ float tile[32][33];
    int n0 = blockIdx.x * 32;
    int c0 = blockIdx.y * 32;
    int b  = blockIdx.z;
    int txx = threadIdx.x, tyy = threadIdx.y;

#pragma unroll
    for (int r = 0; r < 4; ++r) {
        int c = c0 + tyy + r * 8;
        tile[tyy + r * 8][txx] = x[((size_t)b * C + c) * N + n0 + txx];
    }
    __syncthreads();
#pragma unroll
    for (int r = 0; r < 4; ++r) {
        int n = n0 + tyy + r * 8;
        float v = tile[txx][tyy + r * 8] * g_inv[b * N + n];
        g_flat[((size_t)b * N + n) * C + c0 + txx] = __float2bfloat16_rn(v);
    }
}

// ---------------------------------------------------------------------------
// Kernel B: symmetric tile-pair GEMM via mma.sync bf16 (m16n8k16).
// 8 warps: warp grid 2(m) x 4(n); each warp 64x32 = 4x4 fragments.
// SMEM tiles: 128 rows x 64 B (32 bf16), quad-XOR swizzle q' = q ^ ((row>>1)&3)
// -> conflict-free STS.128 and all fragment LDS.32 patterns.
// ---------------------------------------------------------------------------
__device__ __forceinline__ void mma_bf16(float* d, const uint32_t* a,
                                         const uint32_t* bb) {
    asm volatile(
        "mma.sync.aligned.m16n8k16.row.col.f32.bf16.bf16.f32 "
        "{%0,%1,%2,%3}, {%4,%5,%6,%7}, {%8,%9}, {%0,%1,%2,%3};"
        : "+f"(d[0]), "+f"(d[1]), "+f"(d[2]), "+f"(d[3])
        : "r"(a[0]), "r"(a[1]), "r"(a[2]), "r"(a[3]), "r"(bb[0]), "r"(bb[1]));
}

// byte offset of quad q (16B) in row `row` of a swizzled 128x64B tile
__device__ __forceinline__ int toff(int row, int q) {
    return row * 64 + ((q ^ ((row >> 1) & 3)) << 4);
}

__global__ void __launch_bounds__(256, 2) kB_bmma() {
    __shared__ __align__(16) char As[TT * 64];
    __shared__ __align__(16) char Bs[TT * 64];
    __shared__ float attA[TT], attB[TT];
    __shared__ float rowsum[TT], colsum[TT];

    int b = blockIdx.y;
    int p = blockIdx.x, ti = 0;
    while (p >= NT - ti) { p -= NT - ti; ++ti; }
    int tj = ti + p;
    bool diag = (ti == tj);
    int n0 = ti * TT, m0 = tj * TT;

    int tid  = threadIdx.x;
    int wid  = tid >> 5, lane = tid & 31;
    int grp  = lane >> 2, qid = lane & 3;
    int mw   = (wid & 1) * 64;        // warp m-offset
    int nw   = (wid >> 1) * 32;       // warp n-offset

    const float* attb = g_att + b * N;
    if (tid < TT) { attA[tid] = attb[n0 + tid]; rowsum[tid] = 0.f; }
    else          { attB[tid - TT] = attb[m0 + tid - TT]; colsum[tid - TT] = 0.f; }

    const __nv_bfloat16* Arow = g_flat + ((size_t)b * N + n0) * C;
    const __nv_bfloat16* Brow = g_flat + ((size_t)b * N + m0) * C;

    int lrow = tid >> 2, lq = tid & 3;   // loader: 64 rows x 4 quads per pass

    float acc[4][4][4];
#pragma unroll
    for (int i = 0; i < 4; ++i)
#pragma unroll
        for (int j = 0; j < 4; ++j)
#pragma unroll
            for (int r = 0; r < 4; ++r) acc[i][j][r] = 0.f;

    for (int kc = 0; kc < NKC; ++kc) {
        int k0 = kc * TK;
        uint4 ra[2], rb[2];
#pragma unroll
        for (int it = 0; it < 2; ++it) {
            int row = it * 64 + lrow;
            ra[it] = *(const uint4*)(Arow + (size_t)row * C + k0 + lq * 8);
            rb[it] = *(const uint4*)(Brow + (size_t)row * C + k0 + lq * 8);
        }
        __syncthreads();   // previous compute done reading smem
#pragma unroll
        for (int it = 0; it < 2; ++it) {
            int row = it * 64 + lrow;
            *(uint4*)(As + toff(row, lq)) = ra[it];
            *(uint4*)(Bs + toff(row, lq)) = rb[it];
        }
        __syncthreads();

#pragma unroll
        for (int ks = 0; ks < 2; ++ks) {
            uint32_t af[4][4], bf[4][2];
#pragma unroll
            for (int fi = 0; fi < 4; ++fi) {
                int r0 = mw + fi * 16 + grp;
                af[fi][0] = *(const uint32_t*)(As + toff(r0,     2 * ks)     + qid * 4);
                af[fi][1] = *(const uint32_t*)(As + toff(r0 + 8, 2 * ks)     + qid * 4);
                af[fi][2] = *(const uint32_t*)(As + toff(r0,     2 * ks + 1) + qid * 4);
                af[fi][3] = *(const uint32_t*)(As + toff(r0 + 8, 2 * ks + 1) + qid * 4);
            }
#pragma unroll
            for (int fj = 0; fj < 4; ++fj) {
                int rn = nw + fj * 8 + grp;
                bf[fj][0] = *(const uint32_t*)(Bs + toff(rn, 2 * ks)     + qid * 4);
                bf[fj][1] = *(const uint32_t*)(Bs + toff(rn, 2 * ks + 1) + qid * 4);
            }
#pragma unroll
            for (int fi = 0; fi < 4; ++fi)
#pragma unroll
                for (int fj = 0; fj < 4; ++fj)
                    mma_bf16(acc[fi][fj], af[fi], bf[fj]);
        }
    }
    __syncthreads();

    // ---- epilogue: relu^2 * att -> per-thread partials -> smem atomics ----
    float rs[4][2], cs[4][2];
#pragma unroll
    for (int i = 0; i < 4; ++i) { rs[i][0] = rs[i][1] = 0.f; cs[i][0] = cs[i][1] = 0.f; }

#pragma unroll
    for (int fi = 0; fi < 4; ++fi) {
        int r0 = mw + fi * 16 + grp, r1 = r0 + 8;
        float aA0 = attA[r0], aA1 = attA[r1];
#pragma unroll
        for (int fj = 0; fj < 4; ++fj) {
            int c0 = nw + fj * 8 + qid * 2, c1 = c0 + 1;
            float s00 = fmaxf(acc[fi][fj][0], 0.f); s00 *= s00;
            float s01 = fmaxf(acc[fi][fj][1], 0.f); s01 *= s01;
            float s10 = fmaxf(acc[fi][fj][2], 0.f); s10 *= s10;
            float s11 = fmaxf(acc[fi][fj][3], 0.f); s11 *= s11;
            float aB0 = attB[c0], aB1 = attB[c1];
            rs[fi][0] = fmaf(s00, aB0, fmaf(s01, aB1, rs[fi][0]));
            rs[fi][1] = fmaf(s10, aB0, fmaf(s11, aB1, rs[fi][1]));
            cs[fj][0] = fmaf(s00, aA0, fmaf(s10, aA1, cs[fj][0]));
            cs[fj][1] = fmaf(s01, aA0, fmaf(s11, aA1, cs[fj][1]));
        }
    }
#pragma unroll
    for (int fi = 0; fi < 4; ++fi) {
        int r0 = mw + fi * 16 + grp;
        atomicAdd(&rowsum[r0], rs[fi][0]);
        atomicAdd(&rowsum[r0 + 8], rs[fi][1]);
    }
    if (!diag) {
#pragma unroll
        for (int fj = 0; fj < 4; ++fj) {
            int c0 = nw + fj * 8 + qid * 2;
            atomicAdd(&colsum[c0], cs[fj][0]);
            atomicAdd(&colsum[c0 + 1], cs[fj][1]);
        }
    }
    __syncthreads();

    float* refb = g_ref + b * N;
    if (tid < TT) {
        atomicAdd(&refb[n0 + tid], rowsum[tid]);
        if (!diag) atomicAdd(&refb[m0 + tid], colsum[tid]);
    }
}

// ---------------------------------------------------------------------------
// Kernel C: out[b,c] = (1/N) * sum_n x[b][c][n] * refine[b][n]
// ---------------------------------------------------------------------------
__global__ void __launch_bounds__(256) kC(const float* __restrict__ x,
                                          float* __restrict__ out) {
    int b  = blockIdx.x >> 6;
    int cg = blockIdx.x & 63;
    int warp = threadIdx.x >> 5, lane = threadIdx.x & 31;
    int c = cg * 8 + warp;

    const float* xr = x + ((size_t)b * C + c) * N;
    const float* rf = g_ref + b * N;

    float s = 0.f;
#pragma unroll 4
    for (int n = lane; n < N; n += 32) s = fmaf(xr[n], rf[n], s);
#pragma unroll
    for (int off = 16; off > 0; off >>= 1)
        s += __shfl_down_sync(0xffffffffu, s, off);
    if (lane == 0) out[b * C + c] = s * (1.0f / (float)N);
}

// ---------------------------------------------------------------------------
extern "C" void kernel_launch(void* const* d_in, const int* in_sizes, int n_in,
                              void* d_out, int out_size) {
    const float* x = (const float*)d_in[0];
    const float* w = (const float*)d_in[1];
    float* out = (float*)d_out;

    kA1<<<dim3(N / 256, B), 256>>>(x, w);
    kA2<<<dim3(N / 32, C / 32, B), dim3(32, 8)>>>(x);
    kB_bmma<<<dim3(NPAIR, B), 256>>>();
    kC<<<B * 64, 256>>>(x, out);
}